// round 16
// baseline (speedup 1.0000x reference)
#include <cuda_runtime.h>
#include <cuda_fp16.h>
#include <mma.h>
#include <cstdint>

using namespace nvcuda;

#define NN_MAX 100000
#define NN_PAD (NN_MAX + 128)
#define EE_MAX 1600000

// ---------------- device scratch (no allocs allowed) ----------------
__device__ __align__(16) int    g_deg[NN_MAX];
__device__ __align__(16) int    g_cursor[NN_MAX];
__device__ __align__(16) float  g_dinv[NN_MAX];
__device__ __align__(16) int    g_off[NN_MAX + 1];
__device__ __align__(16) int    g_offpart[NN_MAX];
__device__ __align__(16) int    g_bsums[128];
__device__ __align__(16) int2   g_edges[EE_MAX];              // packed {src, w}
__device__ __align__(16) __half g_h16[(size_t)NN_PAD * 128];  // gemm out (gather)
__device__ __align__(16) __half g_ha16[(size_t)NN_PAD * 128]; // agg1 out (gemm2 A)
__device__ __align__(16) float  g_agg[(size_t)NN_PAD * 8];    // 8-wide fp32
__device__ int g_is64;

// ---------------- edge dtype detection (int64 vs int32) ----------------
__device__ __forceinline__ int edge_at(const void* __restrict__ ei, long long i) {
    if (g_is64) return (int)((const long long*)ei)[i];
    return ((const int*)ei)[i];
}

// ---- load 4 consecutive edge indices starting at i (requires alignment) ----
__device__ __forceinline__ void edge_at4(const void* __restrict__ ei, long long i,
                                         int idx[4]) {
    if (g_is64) {
        const longlong2* p = (const longlong2*)((const long long*)ei + i);
        longlong2 a = p[0];
        longlong2 b = p[1];
        idx[0] = (int)a.x; idx[1] = (int)a.y;
        idx[2] = (int)b.x; idx[3] = (int)b.y;
    } else {
        int4 v = *(const int4*)((const int*)ei + i);
        idx[0] = v.x; idx[1] = v.y; idx[2] = v.z; idx[3] = v.w;
    }
}

// ---------------- init: deg=1 + dtype detect -------------------------------
__global__ void k_init(const int* __restrict__ ei32, int n) {
    int i = blockIdx.x * blockDim.x + threadIdx.x;
    if (i < n) g_deg[i] = 1;                        // self-loop counts 1
    if (i == 0) {
        int is64 = 1;
        #pragma unroll
        for (int k = 1; k < 64; k += 2)
            if (ei32[k] != 0) { is64 = 0; break; }
        g_is64 = is64;
    }
}

// ---------------- degree count: 4 edges/thread, vectorized -----------------
__global__ void k_count(const void* __restrict__ ei, int E, int n, int vecOk) {
    int t = blockIdx.x * blockDim.x + threadIdx.x;
    int e = t * 4;
    if (e >= E) return;
    if (vecOk && e + 4 <= E) {
        int d[4];
        edge_at4(ei, (long long)E + e, d);
        #pragma unroll
        for (int q = 0; q < 4; q++)
            if ((unsigned)d[q] < (unsigned)n) atomicAdd(&g_deg[d[q]], 1);
    } else {
        for (int q = 0; q < 4 && e + q < E; q++) {
            int d = edge_at(ei, (long long)E + e + q);
            if ((unsigned)d < (unsigned)n) atomicAdd(&g_deg[d], 1);
        }
    }
}

// ------- scan pass 1: block-local exclusive scan of (deg-1), + dinv --------
__global__ void k_scan1(int n) {
    __shared__ int sh[1024];
    int t = threadIdx.x;
    int i = blockIdx.x * 1024 + t;
    int deg = (i < n) ? g_deg[i] : 1;
    int c = deg - 1;
    sh[t] = c;
    __syncthreads();
    for (int ofs = 1; ofs < 1024; ofs <<= 1) {
        int v = (t >= ofs) ? sh[t - ofs] : 0;
        __syncthreads();
        sh[t] += v;
        __syncthreads();
    }
    if (i < n) {
        g_offpart[i] = sh[t] - c;                 // exclusive within block
        g_dinv[i] = rsqrtf((float)deg);           // fused normalization
    }
    if (t == 1023) g_bsums[blockIdx.x] = sh[1023];
}

// ------- scan pass 2: final offsets + cursor init ---------------------------
__global__ void k_scan3(int n, int E, int nb) {
    __shared__ int sh[128];
    __shared__ int excl[128];
    int t = threadIdx.x;
    int c = (t < 128 && t < nb) ? g_bsums[t] : 0;
    if (t < 128) sh[t] = c;
    __syncthreads();
    for (int ofs = 1; ofs < 128; ofs <<= 1) {
        int v = (t < 128 && t >= ofs) ? sh[t - ofs] : 0;
        __syncthreads();
        if (t < 128) sh[t] += v;
        __syncthreads();
    }
    if (t < 128) excl[t] = sh[t] - c;
    __syncthreads();
    int i = blockIdx.x * blockDim.x + threadIdx.x;
    if (i < n) {
        int off = g_offpart[i] + excl[i >> 10];
        g_off[i] = off;
        g_cursor[i] = off;                        // sort writes via cursor directly
    }
    if (i == 0) g_off[n] = E;
}

// ------- counting-sort by destination: 4 edges/thread, vectorized ----------
__global__ void k_sort(const void* __restrict__ ei, int E, int n, int vecOk) {
    int t = blockIdx.x * blockDim.x + threadIdx.x;
    int e = t * 4;
    if (e >= E) return;
    if (vecOk && e + 4 <= E) {
        int s[4], d[4];
        edge_at4(ei, e, s);
        edge_at4(ei, (long long)E + e, d);
        #pragma unroll
        for (int q = 0; q < 4; q++) {
            if ((unsigned)s[q] >= (unsigned)n || (unsigned)d[q] >= (unsigned)n) continue;
            int pos = atomicAdd(&g_cursor[d[q]], 1);
            if ((unsigned)pos < (unsigned)EE_MAX) {
                float w = g_dinv[s[q]] * g_dinv[d[q]];
                g_edges[pos] = make_int2(s[q], __float_as_int(w));
            }
        }
    } else {
        for (int q = 0; q < 4 && e + q < E; q++) {
            int s = edge_at(ei, e + q);
            int d = edge_at(ei, (long long)E + e + q);
            if ((unsigned)s >= (unsigned)n || (unsigned)d >= (unsigned)n) continue;
            int pos = atomicAdd(&g_cursor[d], 1);
            if ((unsigned)pos < (unsigned)EE_MAX) {
                float w = g_dinv[s] * g_dinv[d];
                g_edges[pos] = make_int2(s, __float_as_int(w));
            }
        }
    }
}

// -------- tensor-core GEMM -> fp16 table -----------------------------------
union SmemU {
    struct { __half As[128][80]; __half Bs[64][144]; } L;  // 38912 B
    float stage[8][1088];                                   // 8 warps x 16x68
};

__global__ void __launch_bounds__(256, 2)
k_gemm_tc(const float* __restrict__ Aext, int asel,
          const float* __restrict__ B, int M) {
    __shared__ __align__(32) SmemU sm;

    int tid = threadIdx.x;
    int wid = tid >> 5;
    int lane = tid & 31;
    int warp_m = wid >> 1;       // 0..3 : 32-row strip
    int warp_n = wid & 1;        // 0..1 : 64-col strip
    int rowBase = blockIdx.x * 128;

    wmma::fragment<wmma::accumulator, 16, 16, 16, float> cfrag[2][4];
    #pragma unroll
    for (int i = 0; i < 2; i++)
        #pragma unroll
        for (int j = 0; j < 4; j++) wmma::fill_fragment(cfrag[i][j], 0.f);

    #pragma unroll
    for (int p = 0; p < 2; p++) {                  // two 64-wide k phases
        int k0 = p * 64;
        if (asel == 0) {
            for (int i = tid; i < 128 * 16; i += 256) {
                int r = i >> 4;
                int c4 = (i & 15) * 4;
                float4 v = make_float4(0.f, 0.f, 0.f, 0.f);
                int gr = rowBase + r;
                if (gr < M) v = *(const float4*)&Aext[(size_t)gr * 128 + k0 + c4];
                *(__half2*)&sm.L.As[r][c4]     = __floats2half2_rn(v.x, v.y);
                *(__half2*)&sm.L.As[r][c4 + 2] = __floats2half2_rn(v.z, v.w);
            }
        } else {
            for (int i = tid; i < 128 * 8; i += 256) {
                int r = i >> 3;
                int c8 = (i & 7) * 8;
                uint4 v = make_uint4(0u, 0u, 0u, 0u);
                int gr = rowBase + r;
                if (gr < M) v = *(const uint4*)&g_ha16[(size_t)gr * 128 + k0 + c8];
                *(uint4*)&sm.L.As[r][c8] = v;
            }
        }
        for (int i = tid; i < 64 * 32; i += 256) {
            int r = i >> 5;
            int c4 = (i & 31) * 4;
            float4 v = *(const float4*)&B[(size_t)(k0 + r) * 128 + c4];
            *(__half2*)&sm.L.Bs[r][c4]     = __floats2half2_rn(v.x, v.y);
            *(__half2*)&sm.L.Bs[r][c4 + 2] = __floats2half2_rn(v.z, v.w);
        }
        __syncthreads();

        #pragma unroll
        for (int ks = 0; ks < 4; ks++) {
            wmma::fragment<wmma::matrix_a, 16, 16, 16, __half, wmma::row_major> af[2];
            wmma::fragment<wmma::matrix_b, 16, 16, 16, __half, wmma::row_major> bf[4];
            #pragma unroll
            for (int i = 0; i < 2; i++)
                wmma::load_matrix_sync(af[i], &sm.L.As[warp_m * 32 + i * 16][ks * 16], 80);
            #pragma unroll
            for (int j = 0; j < 4; j++)
                wmma::load_matrix_sync(bf[j], &sm.L.Bs[ks * 16][warp_n * 64 + j * 16], 144);
            #pragma unroll
            for (int i = 0; i < 2; i++)
                #pragma unroll
                for (int j = 0; j < 4; j++)
                    wmma::mma_sync(cfrag[i][j], af[i], bf[j], cfrag[i][j]);
        }
        __syncthreads();
    }

    // epilogue: fragments -> smem stage (fp32) -> fp16 global (coalesced)
    float* stg = sm.stage[wid];
    #pragma unroll
    for (int i = 0; i < 2; i++) {
        int r0 = rowBase + warp_m * 32 + i * 16;
        if (r0 >= M) continue;
        #pragma unroll
        for (int j = 0; j < 4; j++)
            wmma::store_matrix_sync(&stg[j * 16], cfrag[i][j], 68, wmma::mem_row_major);
        __syncwarp();
        #pragma unroll
        for (int r = 0; r < 16; r++) {
            float2 v = *(const float2*)&stg[r * 68 + 2 * lane];
            *(__half2*)&g_h16[(size_t)(r0 + r) * 128 + warp_n * 64 + 2 * lane] =
                __floats2half2_rn(v.x, v.y);
        }
        __syncwarp();
    }
}

// ---- fp16 row fragment -> 4 floats ----------------------------------------
__device__ __forceinline__ void load_h4(const uint2* __restrict__ h2p,
                                        size_t idx, float4& f) {
    uint2 raw = h2p[idx];
    __half2 p0 = *reinterpret_cast<__half2*>(&raw.x);
    __half2 p1 = *reinterpret_cast<__half2*>(&raw.y);
    float2 f0 = __half22float2(p0);
    float2 f1 = __half22float2(p1);
    f.x = f0.x; f.y = f0.y; f.z = f1.x; f.w = f1.y;
}

// ---------------- aggregation F=128 (layer 1): gather g_h16 -> g_ha16 ------
__global__ void k_agg128(const float* __restrict__ bias, int n) {
    int node = (blockIdx.x * blockDim.x + threadIdx.x) >> 5;
    int lane = threadIdx.x & 31;
    if (node >= n) return;

    const uint2* h2p = reinterpret_cast<const uint2*>((const __half*)g_h16);

    float dv = g_dinv[node];
    float sw = dv * dv;
    float4 self;
    load_h4(h2p, (size_t)node * 32 + lane, self);
    float4 acc = make_float4(self.x * sw, self.y * sw, self.z * sw, self.w * sw);

    int e0 = g_off[node];
    int e1 = g_off[node + 1];
    for (int e = e0; e < e1; e++) {
        int2 ed = g_edges[e];                     // broadcast LDG.64
        float we = __int_as_float(ed.y);
        float4 v;
        load_h4(h2p, (size_t)ed.x * 32 + lane, v);
        acc.x = fmaf(v.x, we, acc.x);
        acc.y = fmaf(v.y, we, acc.y);
        acc.z = fmaf(v.z, we, acc.z);
        acc.w = fmaf(v.w, we, acc.w);
    }
    float4 b = reinterpret_cast<const float4*>(bias)[lane];
    acc.x = fmaxf(acc.x + b.x, 0.f);
    acc.y = fmaxf(acc.y + b.y, 0.f);
    acc.z = fmaxf(acc.z + b.z, 0.f);
    acc.w = fmaxf(acc.w + b.w, 0.f);
    uint2 o;
    __half2 h0 = __floats2half2_rn(acc.x, acc.y);
    __half2 h1 = __floats2half2_rn(acc.z, acc.w);
    o.x = *(unsigned*)&h0;
    o.y = *(unsigned*)&h1;
    reinterpret_cast<uint2*>((__half*)g_ha16)[(size_t)node * 32 + lane] = o;
}

// ------- aggregation F=128 (layer 2) fused with 128->8 projection ----------
__global__ void k_agg128_proj(const float* __restrict__ bias,
                              const float* __restrict__ W3, int n) {
    __shared__ __align__(16) float Wt[8 * 132];
    for (int i = threadIdx.x; i < 1024; i += blockDim.x) {
        int k = i >> 3, j = i & 7;                 // W3 is [128][8] row-major
        Wt[j * 132 + k] = W3[i];
    }
    __syncthreads();

    int node = (blockIdx.x * blockDim.x + threadIdx.x) >> 5;
    int lane = threadIdx.x & 31;
    if (node >= n) return;

    const uint2* h2p = reinterpret_cast<const uint2*>((const __half*)g_h16);

    float dv = g_dinv[node];
    float sw = dv * dv;
    float4 self;
    load_h4(h2p, (size_t)node * 32 + lane, self);
    float4 acc = make_float4(self.x * sw, self.y * sw, self.z * sw, self.w * sw);

    int e0 = g_off[node];
    int e1 = g_off[node + 1];
    for (int e = e0; e < e1; e++) {
        int2 ed = g_edges[e];
        float we = __int_as_float(ed.y);
        float4 v;
        load_h4(h2p, (size_t)ed.x * 32 + lane, v);
        acc.x = fmaf(v.x, we, acc.x);
        acc.y = fmaf(v.y, we, acc.y);
        acc.z = fmaf(v.z, we, acc.z);
        acc.w = fmaf(v.w, we, acc.w);
    }
    float4 b = reinterpret_cast<const float4*>(bias)[lane];
    acc.x = fmaxf(acc.x + b.x, 0.f);
    acc.y = fmaxf(acc.y + b.y, 0.f);
    acc.z = fmaxf(acc.z + b.z, 0.f);
    acc.w = fmaxf(acc.w + b.w, 0.f);

    // project: y[j] = this lane's k-slice (k = 4*lane + c) of h2 @ W3
    int kb = lane * 4;
    float y[8];
    #pragma unroll
    for (int j = 0; j < 8; j++) {
        float4 w = *reinterpret_cast<const float4*>(&Wt[j * 132 + kb]);
        float p = acc.x * w.x;
        p = fmaf(acc.y, w.y, p);
        p = fmaf(acc.z, w.z, p);
        p = fmaf(acc.w, w.w, p);
        y[j] = p;
    }
    #pragma unroll
    for (int j = 0; j < 8; j++) {
        #pragma unroll
        for (int ofs = 16; ofs > 0; ofs >>= 1)
            y[j] += __shfl_xor_sync(0xffffffffu, y[j], ofs);
    }
    if (lane < 8) g_agg[(size_t)node * 8 + lane] = y[lane];
}

// ------- aggregation F=8 fused with classifier (8->16) ---------------------
__global__ void k_agg8cls(const float* __restrict__ b3,
                          const float* __restrict__ Wc,
                          const float* __restrict__ bc,
                          float* __restrict__ out, int n) {
    __shared__ float Ws[8 * 16];
    __shared__ float bs[16];
    if (threadIdx.x < 128) Ws[threadIdx.x] = Wc[threadIdx.x];
    if (threadIdx.x < 16) bs[threadIdx.x] = bc[threadIdx.x];
    __syncthreads();

    int t = blockIdx.x * blockDim.x + threadIdx.x;
    int node = t >> 3;
    int f = t & 7;
    if (node >= n) return;

    float dv = g_dinv[node];
    float acc = g_agg[(size_t)node * 8 + f] * dv * dv;
    int e0 = g_off[node];
    int e1 = g_off[node + 1];
    for (int e = e0; e < e1; e++) {
        int2 ed = g_edges[e];
        acc = fmaf(g_agg[(size_t)ed.x * 8 + f], __int_as_float(ed.y), acc);
    }
    float h3 = fmaxf(acc + b3[f], 0.f);

    unsigned mask = 0xffffffffu;
    int base = (threadIdx.x & 31) & ~7;
    float o0 = bs[f], o1 = bs[f + 8];
    #pragma unroll
    for (int fp = 0; fp < 8; fp++) {
        float hv = __shfl_sync(mask, h3, base + fp);
        o0 = fmaf(hv, Ws[fp * 16 + f], o0);
        o1 = fmaf(hv, Ws[fp * 16 + f + 8], o1);
    }
    out[(size_t)node * 16 + f] = o0;
    out[(size_t)node * 16 + f + 8] = o1;
}

// ---------------- launch: prep on side stream ∥ gemm1 on main ----------------
extern "C" void kernel_launch(void* const* d_in, const int* in_sizes, int n_in,
                              void* d_out, int out_size) {
    const float* x  = (const float*)d_in[0];
    const void*  ei = d_in[1];
    const float* W1 = (const float*)d_in[2];
    const float* b1 = (const float*)d_in[3];
    const float* W2 = (const float*)d_in[4];
    const float* b2 = (const float*)d_in[5];
    const float* W3 = (const float*)d_in[6];
    const float* b3 = (const float*)d_in[7];
    const float* Wc = (const float*)d_in[8];
    const float* bc = (const float*)d_in[9];
    float* out = (float*)d_out;

    int n = in_sizes[0] / 128;
    int E = in_sizes[1] / 2;

    int gemmGrid = (n + 127) / 128;
    int aggGrid128 = (int)(((long long)n * 32 + 255) / 256);
    int nb = (n + 1023) / 1024;
    int eQuadGrid = (int)(((long long)E / 4 + 256) / 256);   // 4 edges/thread
    int vecOk = ((E & 3) == 0) ? 1 : 0;                      // 16B-aligned vec loads

    cudaStream_t s2 = nullptr;
    cudaEvent_t eFork = nullptr, eJoin = nullptr;
    bool forked = (cudaStreamCreateWithFlags(&s2, cudaStreamNonBlocking) == cudaSuccess);
    if (forked) {
        forked = (cudaEventCreateWithFlags(&eFork, cudaEventDisableTiming) == cudaSuccess) &&
                 (cudaEventCreateWithFlags(&eJoin, cudaEventDisableTiming) == cudaSuccess);
    }

    if (forked) {
        cudaEventRecord(eFork, 0);
        cudaStreamWaitEvent(s2, eFork, 0);
        k_init<<<(n + 255) / 256, 256, 0, s2>>>((const int*)ei, n);
        k_count<<<eQuadGrid, 256, 0, s2>>>(ei, E, n, vecOk);
        k_scan1<<<nb, 1024, 0, s2>>>(n);
        k_scan3<<<(n + 255) / 256, 256, 0, s2>>>(n, E, nb);
        k_sort<<<eQuadGrid, 256, 0, s2>>>(ei, E, n, vecOk);
        cudaEventRecord(eJoin, s2);
        // concurrent: layer-1 GEMM on the capture stream
        k_gemm_tc<<<gemmGrid, 256>>>(x, 0, W1, n);
        cudaStreamWaitEvent(0, eJoin, 0);
    } else {
        k_init<<<(n + 255) / 256, 256>>>((const int*)ei, n);
        k_count<<<eQuadGrid, 256>>>(ei, E, n, vecOk);
        k_scan1<<<nb, 1024>>>(n);
        k_scan3<<<(n + 255) / 256, 256>>>(n, E, nb);
        k_sort<<<eQuadGrid, 256>>>(ei, E, n, vecOk);
        k_gemm_tc<<<gemmGrid, 256>>>(x, 0, W1, n);
    }

    // layer 1 agg: g_h16 -> g_ha16 (fp16)
    k_agg128<<<aggGrid128, 256>>>(b1, n);
    // layer 2: g_h16 = fp16(g_ha16@W2) ; agg+relu+b2+@W3 -> g_agg (8w fp32)
    k_gemm_tc<<<gemmGrid, 256>>>(nullptr, 1, W2, n);
    k_agg128_proj<<<aggGrid128, 256>>>(b2, W3, n);
    // layer 3 agg + b3 + relu + classifier: g_agg -> out
    k_agg8cls<<<(int)(((long long)n * 8 + 255) / 256), 256>>>(b3, Wc, bc, out, n);

    if (eFork) cudaEventDestroy(eFork);
    if (eJoin) cudaEventDestroy(eJoin);
    if (s2) cudaStreamDestroy(s2);
}

// round 17
// speedup vs baseline: 1.0045x; 1.0045x over previous
#include <cuda_runtime.h>
#include <cuda_fp16.h>
#include <mma.h>
#include <cstdint>

using namespace nvcuda;

#define NN_MAX 100000
#define NN_PAD (NN_MAX + 128)
#define EE_MAX 1600000

// ---------------- device scratch (no allocs allowed) ----------------
__device__ __align__(16) int    g_deg[NN_MAX];     // raw counts; reset by scan1
__device__ __align__(16) int    g_cursor[NN_MAX];
__device__ __align__(16) float  g_dinv[NN_MAX];
__device__ __align__(16) int    g_off[NN_MAX + 1];
__device__ __align__(16) int    g_offpart[NN_MAX];
__device__ __align__(16) int    g_bsums[128];
__device__ __align__(16) int2   g_edges[EE_MAX];              // packed {src, w}
__device__ __align__(16) __half g_h16[(size_t)NN_PAD * 128];  // gemm out (gather)
__device__ __align__(16) __half g_ha16[(size_t)NN_PAD * 128]; // agg1 out (gemm2 A)
__device__ __align__(16) float  g_agg[(size_t)NN_PAD * 8];    // 8-wide fp32
__device__ int g_is64;

// ---------------- edge dtype detection (int64 vs int32) ----------------
__device__ __forceinline__ int edge_at(const void* __restrict__ ei, long long i) {
    if (g_is64) return (int)((const long long*)ei)[i];
    return ((const int*)ei)[i];
}

// ---------------- tiny: dtype detect only ----------------------------------
__global__ void k_detect(const int* __restrict__ ei32) {
    if (threadIdx.x == 0) {
        int is64 = 1;
        #pragma unroll
        for (int k = 1; k < 64; k += 2)
            if (ei32[k] != 0) { is64 = 0; break; }
        g_is64 = is64;
    }
}

// ---------------- degree count: 2 edges per thread (zero-based counts) -----
__global__ void k_count(const void* __restrict__ ei, int E, int n) {
    int t = blockIdx.x * blockDim.x + threadIdx.x;
    int e = t * 2;
    if (e >= E) return;
    int d0 = edge_at(ei, (long long)E + e);
    if ((unsigned)d0 < (unsigned)n) atomicAdd(&g_deg[d0], 1);
    if (e + 1 < E) {
        int d1 = edge_at(ei, (long long)E + e + 1);
        if ((unsigned)d1 < (unsigned)n) atomicAdd(&g_deg[d1], 1);
    }
}

// ------- scan pass 1: exclusive scan of counts, dinv, deg reset -------------
__global__ void k_scan1(int n) {
    __shared__ int sh[1024];
    int t = threadIdx.x;
    int i = blockIdx.x * 1024 + t;
    int cnt = (i < n) ? g_deg[i] : 0;             // edges to dst i (self-loop excl.)
    sh[t] = cnt;
    __syncthreads();
    for (int ofs = 1; ofs < 1024; ofs <<= 1) {
        int v = (t >= ofs) ? sh[t - ofs] : 0;
        __syncthreads();
        sh[t] += v;
        __syncthreads();
    }
    if (i < n) {
        g_offpart[i] = sh[t] - cnt;               // exclusive within block
        g_dinv[i] = rsqrtf((float)(cnt + 1));     // deg includes self-loop
        g_deg[i] = 0;                             // reset for next replay
    }
    if (t == 1023) g_bsums[blockIdx.x] = sh[1023];
}

// ------- scan pass 2: final offsets + cursor init ---------------------------
__global__ void k_scan3(int n, int E, int nb) {
    __shared__ int sh[128];
    __shared__ int excl[128];
    int t = threadIdx.x;
    int c = (t < 128 && t < nb) ? g_bsums[t] : 0;
    if (t < 128) sh[t] = c;
    __syncthreads();
    for (int ofs = 1; ofs < 128; ofs <<= 1) {
        int v = (t < 128 && t >= ofs) ? sh[t - ofs] : 0;
        __syncthreads();
        if (t < 128) sh[t] += v;
        __syncthreads();
    }
    if (t < 128) excl[t] = sh[t] - c;
    __syncthreads();
    int i = blockIdx.x * blockDim.x + threadIdx.x;
    if (i < n) {
        int off = g_offpart[i] + excl[i >> 10];
        g_off[i] = off;
        g_cursor[i] = off;                        // sort writes via cursor directly
    }
    if (i == 0) g_off[n] = E;
}

// ------- counting-sort by destination: 2 edges/thread, direct cursor -------
__global__ void k_sort(const void* __restrict__ ei, int E, int n) {
    int t = blockIdx.x * blockDim.x + threadIdx.x;
    int e = t * 2;
    if (e >= E) return;
    #pragma unroll
    for (int q = 0; q < 2; q++) {
        int ee = e + q;
        if (ee >= E) break;
        int s = edge_at(ei, ee);
        int d = edge_at(ei, (long long)E + ee);
        if ((unsigned)s >= (unsigned)n || (unsigned)d >= (unsigned)n) continue;
        int pos = atomicAdd(&g_cursor[d], 1);
        if ((unsigned)pos < (unsigned)EE_MAX) {
            float w = g_dinv[s] * g_dinv[d];
            g_edges[pos] = make_int2(s, __float_as_int(w));
        }
    }
}

// -------- tensor-core GEMM -> fp16 table -----------------------------------
union SmemU {
    struct { __half As[128][80]; __half Bs[64][144]; } L;  // 38912 B
    float stage[8][1088];                                   // 8 warps x 16x68
};

__global__ void __launch_bounds__(256, 2)
k_gemm_tc(const float* __restrict__ Aext, int asel,
          const float* __restrict__ B, int M) {
    __shared__ __align__(32) SmemU sm;

    int tid = threadIdx.x;
    int wid = tid >> 5;
    int lane = tid & 31;
    int warp_m = wid >> 1;       // 0..3 : 32-row strip
    int warp_n = wid & 1;        // 0..1 : 64-col strip
    int rowBase = blockIdx.x * 128;

    wmma::fragment<wmma::accumulator, 16, 16, 16, float> cfrag[2][4];
    #pragma unroll
    for (int i = 0; i < 2; i++)
        #pragma unroll
        for (int j = 0; j < 4; j++) wmma::fill_fragment(cfrag[i][j], 0.f);

    #pragma unroll
    for (int p = 0; p < 2; p++) {                  // two 64-wide k phases
        int k0 = p * 64;
        if (asel == 0) {
            for (int i = tid; i < 128 * 16; i += 256) {
                int r = i >> 4;
                int c4 = (i & 15) * 4;
                float4 v = make_float4(0.f, 0.f, 0.f, 0.f);
                int gr = rowBase + r;
                if (gr < M) v = *(const float4*)&Aext[(size_t)gr * 128 + k0 + c4];
                *(__half2*)&sm.L.As[r][c4]     = __floats2half2_rn(v.x, v.y);
                *(__half2*)&sm.L.As[r][c4 + 2] = __floats2half2_rn(v.z, v.w);
            }
        } else {
            for (int i = tid; i < 128 * 8; i += 256) {
                int r = i >> 3;
                int c8 = (i & 7) * 8;
                uint4 v = make_uint4(0u, 0u, 0u, 0u);
                int gr = rowBase + r;
                if (gr < M) v = *(const uint4*)&g_ha16[(size_t)gr * 128 + k0 + c8];
                *(uint4*)&sm.L.As[r][c8] = v;
            }
        }
        for (int i = tid; i < 64 * 32; i += 256) {
            int r = i >> 5;
            int c4 = (i & 31) * 4;
            float4 v = *(const float4*)&B[(size_t)(k0 + r) * 128 + c4];
            *(__half2*)&sm.L.Bs[r][c4]     = __floats2half2_rn(v.x, v.y);
            *(__half2*)&sm.L.Bs[r][c4 + 2] = __floats2half2_rn(v.z, v.w);
        }
        __syncthreads();

        #pragma unroll
        for (int ks = 0; ks < 4; ks++) {
            wmma::fragment<wmma::matrix_a, 16, 16, 16, __half, wmma::row_major> af[2];
            wmma::fragment<wmma::matrix_b, 16, 16, 16, __half, wmma::row_major> bf[4];
            #pragma unroll
            for (int i = 0; i < 2; i++)
                wmma::load_matrix_sync(af[i], &sm.L.As[warp_m * 32 + i * 16][ks * 16], 80);
            #pragma unroll
            for (int j = 0; j < 4; j++)
                wmma::load_matrix_sync(bf[j], &sm.L.Bs[ks * 16][warp_n * 64 + j * 16], 144);
            #pragma unroll
            for (int i = 0; i < 2; i++)
                #pragma unroll
                for (int j = 0; j < 4; j++)
                    wmma::mma_sync(cfrag[i][j], af[i], bf[j], cfrag[i][j]);
        }
        __syncthreads();
    }

    // epilogue: fragments -> smem stage (fp32) -> fp16 global (coalesced)
    float* stg = sm.stage[wid];
    #pragma unroll
    for (int i = 0; i < 2; i++) {
        int r0 = rowBase + warp_m * 32 + i * 16;
        if (r0 >= M) continue;
        #pragma unroll
        for (int j = 0; j < 4; j++)
            wmma::store_matrix_sync(&stg[j * 16], cfrag[i][j], 68, wmma::mem_row_major);
        __syncwarp();
        #pragma unroll
        for (int r = 0; r < 16; r++) {
            float2 v = *(const float2*)&stg[r * 68 + 2 * lane];
            *(__half2*)&g_h16[(size_t)(r0 + r) * 128 + warp_n * 64 + 2 * lane] =
                __floats2half2_rn(v.x, v.y);
        }
        __syncwarp();
    }
}

// ---- fp16 row fragment -> 4 floats ----------------------------------------
__device__ __forceinline__ void load_h4(const uint2* __restrict__ h2p,
                                        size_t idx, float4& f) {
    uint2 raw = h2p[idx];
    __half2 p0 = *reinterpret_cast<__half2*>(&raw.x);
    __half2 p1 = *reinterpret_cast<__half2*>(&raw.y);
    float2 f0 = __half22float2(p0);
    float2 f1 = __half22float2(p1);
    f.x = f0.x; f.y = f0.y; f.z = f1.x; f.w = f1.y;
}

// ---------------- aggregation F=128 (layer 1): gather g_h16 -> g_ha16 ------
__global__ void k_agg128(const float* __restrict__ bias, int n) {
    int node = (blockIdx.x * blockDim.x + threadIdx.x) >> 5;
    int lane = threadIdx.x & 31;
    if (node >= n) return;

    const uint2* h2p = reinterpret_cast<const uint2*>((const __half*)g_h16);

    float dv = g_dinv[node];
    float sw = dv * dv;
    float4 self;
    load_h4(h2p, (size_t)node * 32 + lane, self);
    float4 acc = make_float4(self.x * sw, self.y * sw, self.z * sw, self.w * sw);

    int e0 = g_off[node];
    int e1 = g_off[node + 1];
    for (int e = e0; e < e1; e++) {
        int2 ed = g_edges[e];                     // broadcast LDG.64
        float we = __int_as_float(ed.y);
        float4 v;
        load_h4(h2p, (size_t)ed.x * 32 + lane, v);
        acc.x = fmaf(v.x, we, acc.x);
        acc.y = fmaf(v.y, we, acc.y);
        acc.z = fmaf(v.z, we, acc.z);
        acc.w = fmaf(v.w, we, acc.w);
    }
    float4 b = reinterpret_cast<const float4*>(bias)[lane];
    acc.x = fmaxf(acc.x + b.x, 0.f);
    acc.y = fmaxf(acc.y + b.y, 0.f);
    acc.z = fmaxf(acc.z + b.z, 0.f);
    acc.w = fmaxf(acc.w + b.w, 0.f);
    uint2 o;
    __half2 h0 = __floats2half2_rn(acc.x, acc.y);
    __half2 h1 = __floats2half2_rn(acc.z, acc.w);
    o.x = *(unsigned*)&h0;
    o.y = *(unsigned*)&h1;
    reinterpret_cast<uint2*>((__half*)g_ha16)[(size_t)node * 32 + lane] = o;
}

// ------- aggregation F=128 (layer 2) fused with 128->8 projection ----------
__global__ void k_agg128_proj(const float* __restrict__ bias,
                              const float* __restrict__ W3, int n) {
    __shared__ __align__(16) float Wt[8 * 132];
    for (int i = threadIdx.x; i < 1024; i += blockDim.x) {
        int k = i >> 3, j = i & 7;                 // W3 is [128][8] row-major
        Wt[j * 132 + k] = W3[i];
    }
    __syncthreads();

    int node = (blockIdx.x * blockDim.x + threadIdx.x) >> 5;
    int lane = threadIdx.x & 31;
    if (node >= n) return;

    const uint2* h2p = reinterpret_cast<const uint2*>((const __half*)g_h16);

    float dv = g_dinv[node];
    float sw = dv * dv;
    float4 self;
    load_h4(h2p, (size_t)node * 32 + lane, self);
    float4 acc = make_float4(self.x * sw, self.y * sw, self.z * sw, self.w * sw);

    int e0 = g_off[node];
    int e1 = g_off[node + 1];
    for (int e = e0; e < e1; e++) {
        int2 ed = g_edges[e];
        float we = __int_as_float(ed.y);
        float4 v;
        load_h4(h2p, (size_t)ed.x * 32 + lane, v);
        acc.x = fmaf(v.x, we, acc.x);
        acc.y = fmaf(v.y, we, acc.y);
        acc.z = fmaf(v.z, we, acc.z);
        acc.w = fmaf(v.w, we, acc.w);
    }
    float4 b = reinterpret_cast<const float4*>(bias)[lane];
    acc.x = fmaxf(acc.x + b.x, 0.f);
    acc.y = fmaxf(acc.y + b.y, 0.f);
    acc.z = fmaxf(acc.z + b.z, 0.f);
    acc.w = fmaxf(acc.w + b.w, 0.f);

    // project: y[j] = this lane's k-slice (k = 4*lane + c) of h2 @ W3
    int kb = lane * 4;
    float y[8];
    #pragma unroll
    for (int j = 0; j < 8; j++) {
        float4 w = *reinterpret_cast<const float4*>(&Wt[j * 132 + kb]);
        float p = acc.x * w.x;
        p = fmaf(acc.y, w.y, p);
        p = fmaf(acc.z, w.z, p);
        p = fmaf(acc.w, w.w, p);
        y[j] = p;
    }
    #pragma unroll
    for (int j = 0; j < 8; j++) {
        #pragma unroll
        for (int ofs = 16; ofs > 0; ofs >>= 1)
            y[j] += __shfl_xor_sync(0xffffffffu, y[j], ofs);
    }
    if (lane < 8) g_agg[(size_t)node * 8 + lane] = y[lane];
}

// ------- aggregation F=8 fused with classifier (8->16) ---------------------
__global__ void k_agg8cls(const float* __restrict__ b3,
                          const float* __restrict__ Wc,
                          const float* __restrict__ bc,
                          float* __restrict__ out, int n) {
    __shared__ float Ws[8 * 16];
    __shared__ float bs[16];
    if (threadIdx.x < 128) Ws[threadIdx.x] = Wc[threadIdx.x];
    if (threadIdx.x < 16) bs[threadIdx.x] = bc[threadIdx.x];
    __syncthreads();

    int t = blockIdx.x * blockDim.x + threadIdx.x;
    int node = t >> 3;
    int f = t & 7;
    if (node >= n) return;

    float dv = g_dinv[node];
    float acc = g_agg[(size_t)node * 8 + f] * dv * dv;
    int e0 = g_off[node];
    int e1 = g_off[node + 1];
    for (int e = e0; e < e1; e++) {
        int2 ed = g_edges[e];
        acc = fmaf(g_agg[(size_t)ed.x * 8 + f], __int_as_float(ed.y), acc);
    }
    float h3 = fmaxf(acc + b3[f], 0.f);

    unsigned mask = 0xffffffffu;
    int base = (threadIdx.x & 31) & ~7;
    float o0 = bs[f], o1 = bs[f + 8];
    #pragma unroll
    for (int fp = 0; fp < 8; fp++) {
        float hv = __shfl_sync(mask, h3, base + fp);
        o0 = fmaf(hv, Ws[fp * 16 + f], o0);
        o1 = fmaf(hv, Ws[fp * 16 + f + 8], o1);
    }
    out[(size_t)node * 16 + f] = o0;
    out[(size_t)node * 16 + f + 8] = o1;
}

// ---------------- launch: prep on side stream ∥ gemm1 on main ----------------
extern "C" void kernel_launch(void* const* d_in, const int* in_sizes, int n_in,
                              void* d_out, int out_size) {
    const float* x  = (const float*)d_in[0];
    const void*  ei = d_in[1];
    const float* W1 = (const float*)d_in[2];
    const float* b1 = (const float*)d_in[3];
    const float* W2 = (const float*)d_in[4];
    const float* b2 = (const float*)d_in[5];
    const float* W3 = (const float*)d_in[6];
    const float* b3 = (const float*)d_in[7];
    const float* Wc = (const float*)d_in[8];
    const float* bc = (const float*)d_in[9];
    float* out = (float*)d_out;

    int n = in_sizes[0] / 128;
    int E = in_sizes[1] / 2;

    int gemmGrid = (n + 127) / 128;
    int aggGrid128 = (int)(((long long)n * 32 + 255) / 256);
    int nb = (n + 1023) / 1024;
    int ePairGrid = (int)(((long long)E / 2 + 256) / 256);   // 2 edges/thread

    cudaStream_t s2 = nullptr;
    cudaEvent_t eFork = nullptr, eJoin = nullptr;
    bool forked = (cudaStreamCreateWithFlags(&s2, cudaStreamNonBlocking) == cudaSuccess);
    if (forked) {
        forked = (cudaEventCreateWithFlags(&eFork, cudaEventDisableTiming) == cudaSuccess) &&
                 (cudaEventCreateWithFlags(&eJoin, cudaEventDisableTiming) == cudaSuccess);
    }

    if (forked) {
        cudaEventRecord(eFork, 0);
        cudaStreamWaitEvent(s2, eFork, 0);
        k_detect<<<1, 32, 0, s2>>>((const int*)ei);
        k_count<<<ePairGrid, 256, 0, s2>>>(ei, E, n);
        k_scan1<<<nb, 1024, 0, s2>>>(n);
        k_scan3<<<(n + 255) / 256, 256, 0, s2>>>(n, E, nb);
        k_sort<<<ePairGrid, 256, 0, s2>>>(ei, E, n);
        cudaEventRecord(eJoin, s2);
        // concurrent: layer-1 GEMM on the capture stream
        k_gemm_tc<<<gemmGrid, 256>>>(x, 0, W1, n);
        cudaStreamWaitEvent(0, eJoin, 0);
    } else {
        k_detect<<<1, 32>>>((const int*)ei);
        k_count<<<ePairGrid, 256>>>(ei, E, n);
        k_scan1<<<nb, 1024>>>(n);
        k_scan3<<<(n + 255) / 256, 256>>>(n, E, nb);
        k_sort<<<ePairGrid, 256>>>(ei, E, n);
        k_gemm_tc<<<gemmGrid, 256>>>(x, 0, W1, n);
    }

    // layer 1 agg: g_h16 -> g_ha16 (fp16)
    k_agg128<<<aggGrid128, 256>>>(b1, n);
    // layer 2: g_h16 = fp16(g_ha16@W2) ; agg+relu+b2+@W3 -> g_agg (8w fp32)
    k_gemm_tc<<<gemmGrid, 256>>>(nullptr, 1, W2, n);
    k_agg128_proj<<<aggGrid128, 256>>>(b2, W3, n);
    // layer 3 agg + b3 + relu + classifier: g_agg -> out
    k_agg8cls<<<(int)(((long long)n * 8 + 255) / 256), 256>>>(b3, Wc, bc, out, n);

    if (eFork) cudaEventDestroy(eFork);
    if (eJoin) cudaEventDestroy(eJoin);
    if (s2) cudaStreamDestroy(s2);
}